// round 6
// baseline (speedup 1.0000x reference)
#include <cuda_runtime.h>

// Analytic bi-Laplacian of f(x) = tanh(x W1^T) W2^T.
//   out[b,o] = sum_h W2[o,h] * (||W1[h,:]||^2)^2 * tanh''''(a_{b,h})
//   tanh''''(u) = 8 t (1 - t^2)(2 - 3 t^2),  t = tanh(u)
//
// One warp per batch row. ALL loads issued up-front (max MLP, single
// latency exposure since L1D is cold every launch). Folded 9-shuffle
// reduction instead of 40-shuffle butterfly.
// (Identical to R4 submission — R4 run died to cudaErrorSystemNotReady
// during harness device init, an infra failure, before the kernel ran.)

#define B_DIM 256
#define D_DIM 16
#define H_DIM 128
#define O_DIM 8

__device__ __forceinline__ float ex2_approx(float x) {
    float r;
    asm("ex2.approx.f32 %0, %1;" : "=f"(r) : "f"(x));
    return r;
}
__device__ __forceinline__ float rcp_approx(float x) {
    float r;
    asm("rcp.approx.f32 %0, %1;" : "=f"(r) : "f"(x));
    return r;
}

__global__ __launch_bounds__(128, 1) void bilap_kernel(
    const float* __restrict__ x,    // (256, 16)
    const float* __restrict__ W1,   // (128, 16)
    const float* __restrict__ W2,   // (8, 128)
    float* __restrict__ out)        // (256, 8)
{
    const int b    = blockIdx.x * 4 + (threadIdx.x >> 5); // batch row
    const int lane = threadIdx.x & 31;

    // ---------------- load burst: everything, before any FLOP -------------
    const float4* xv = reinterpret_cast<const float4*>(x + b * D_DIM);
    const float4 x0 = xv[0], x1 = xv[1], x2 = xv[2], x3 = xv[3];

    float4 w[4][4];  // w[k][i] = W1[lane+32k][4i..4i+3]
#pragma unroll
    for (int k = 0; k < 4; k++) {
        const float4* w1 = reinterpret_cast<const float4*>(W1 + (lane + 32 * k) * D_DIM);
#pragma unroll
        for (int i = 0; i < 4; i++) w[k][i] = w1[i];
    }

    float w2v[4][O_DIM];  // W2[o][lane+32k]
#pragma unroll
    for (int k = 0; k < 4; k++)
#pragma unroll
        for (int o = 0; o < O_DIM; o++)
            w2v[k][o] = __ldg(W2 + o * H_DIM + lane + 32 * k);

    // ---------------- compute --------------------------------------------
    const float LOG2E_X2 = 2.8853900817779268f;  // 2*log2(e)
    float acc[O_DIM];
#pragma unroll
    for (int o = 0; o < O_DIM; o++) acc[o] = 0.f;

#pragma unroll
    for (int k = 0; k < 4; k++) {
        const float4 wa = w[k][0], wb = w[k][1], wc = w[k][2], wd = w[k][3];

        float a0 = wa.x * x0.x, a1 = wc.x * x2.x;
        a0 = fmaf(wa.y, x0.y, a0); a1 = fmaf(wc.y, x2.y, a1);
        a0 = fmaf(wa.z, x0.z, a0); a1 = fmaf(wc.z, x2.z, a1);
        a0 = fmaf(wa.w, x0.w, a0); a1 = fmaf(wc.w, x2.w, a1);
        a0 = fmaf(wb.x, x1.x, a0); a1 = fmaf(wd.x, x3.x, a1);
        a0 = fmaf(wb.y, x1.y, a0); a1 = fmaf(wd.y, x3.y, a1);
        a0 = fmaf(wb.z, x1.z, a0); a1 = fmaf(wd.z, x3.z, a1);
        a0 = fmaf(wb.w, x1.w, a0); a1 = fmaf(wd.w, x3.w, a1);
        const float a = a0 + a1;

        float s0 = wa.x * wa.x, s1 = wc.x * wc.x;
        s0 = fmaf(wa.y, wa.y, s0); s1 = fmaf(wc.y, wc.y, s1);
        s0 = fmaf(wa.z, wa.z, s0); s1 = fmaf(wc.z, wc.z, s1);
        s0 = fmaf(wa.w, wa.w, s0); s1 = fmaf(wc.w, wc.w, s1);
        s0 = fmaf(wb.x, wb.x, s0); s1 = fmaf(wd.x, wd.x, s1);
        s0 = fmaf(wb.y, wb.y, s0); s1 = fmaf(wd.y, wd.y, s1);
        s0 = fmaf(wb.z, wb.z, s0); s1 = fmaf(wd.z, wd.z, s1);
        s0 = fmaf(wb.w, wb.w, s0); s1 = fmaf(wd.w, wd.w, s1);
        const float s = s0 + s1;

        // t = tanh(a) = 1 - 2/(exp(2a)+1); saturates correctly.
        const float e  = ex2_approx(a * LOG2E_X2);
        const float t  = fmaf(-2.f, rcp_approx(e + 1.f), 1.f);
        const float t2 = t * t;
        const float g  = 8.f * t * (1.f - t2) * (2.f - 3.f * t2);
        const float c  = g * s * s;

#pragma unroll
        for (int o = 0; o < O_DIM; o++)
            acc[o] = fmaf(c, w2v[k][o], acc[o]);
    }

    // ---------------- folded reduction: 9 shuffles, depth 5 ---------------
    const unsigned FULL = 0xffffffffu;

    // off=16: 8 accs -> 4. lanes bit4=0 keep o in [0,4), bit4=1 keep o in [4,8)
    float r4[4];
#pragma unroll
    for (int o = 0; o < 4; o++) {
        float send = (lane & 16) ? acc[o] : acc[o + 4];
        float keep = (lane & 16) ? acc[o + 4] : acc[o];
        r4[o] = keep + __shfl_xor_sync(FULL, send, 16);
    }
    // off=8: 4 -> 2
    float r2[2];
#pragma unroll
    for (int o = 0; o < 2; o++) {
        float send = (lane & 8) ? r4[o] : r4[o + 2];
        float keep = (lane & 8) ? r4[o + 2] : r4[o];
        r2[o] = keep + __shfl_xor_sync(FULL, send, 8);
    }
    // off=4: 2 -> 1
    float send = (lane & 4) ? r2[0] : r2[1];
    float keep = (lane & 4) ? r2[1] : r2[0];
    float r = keep + __shfl_xor_sync(FULL, send, 4);
    // off=2,1: finish the lane-group sums
    r += __shfl_xor_sync(FULL, r, 2);
    r += __shfl_xor_sync(FULL, r, 1);

    // lane group (L>>2) holds output index o = bit4*4 + bit3*2 + bit2
    if ((lane & 3) == 0) {
        const int o = ((lane & 16) ? 4 : 0) | ((lane & 8) ? 2 : 0) | ((lane & 4) ? 1 : 0);
        out[b * O_DIM + o] = r;
    }
}

extern "C" void kernel_launch(void* const* d_in, const int* in_sizes, int n_in,
                              void* d_out, int out_size) {
    const float* x  = (const float*)d_in[0];   // 256*16
    const float* W1 = (const float*)d_in[1];   // 128*16
    const float* W2 = (const float*)d_in[2];   // 8*128
    float* out = (float*)d_out;                // 256*8
    bilap_kernel<<<64, 128>>>(x, W1, W2, out);
}

// round 7
// speedup vs baseline: 1.0386x; 1.0386x over previous
#include <cuda_runtime.h>

// Analytic bi-Laplacian of f(x) = tanh(x W1^T) W2^T.
//   out[b,o] = sum_h W2[o,h] * (||W1[h,:]||^2)^2 * tanh''''(a_{b,h})
//   tanh''''(u) = 8 t (1 - t^2)(2 - 3 t^2),  t = tanh(u)
//
// TWO batch rows per warp: W1/W2 register tiles shared across rows
// (22% fewer LDGs chip-wide), 128 warps total (grid 32 x 128).
// All loads front-batched (max MLP, single cold-L1 latency exposure).
// 16-accumulator folded shuffle reduction: 16 shuffles, depth 5.

#define B_DIM 256
#define D_DIM 16
#define H_DIM 128
#define O_DIM 8

__device__ __forceinline__ float ex2_approx(float x) {
    float r;
    asm("ex2.approx.f32 %0, %1;" : "=f"(r) : "f"(x));
    return r;
}
__device__ __forceinline__ float rcp_approx(float x) {
    float r;
    asm("rcp.approx.f32 %0, %1;" : "=f"(r) : "f"(x));
    return r;
}

__global__ __launch_bounds__(128, 1) void bilap_kernel(
    const float* __restrict__ x,    // (256, 16)
    const float* __restrict__ W1,   // (128, 16)
    const float* __restrict__ W2,   // (8, 128)
    float* __restrict__ out)        // (256, 8)
{
    const int warp = blockIdx.x * 4 + (threadIdx.x >> 5);
    const int b0   = warp * 2;          // this warp's two batch rows: b0, b0+1
    const int lane = threadIdx.x & 31;

    // ---------------- load burst: everything, before any FLOP -------------
    const float4* xv0 = reinterpret_cast<const float4*>(x + b0 * D_DIM);
    const float4* xv1 = reinterpret_cast<const float4*>(x + (b0 + 1) * D_DIM);
    const float4 p0 = xv0[0], p1 = xv0[1], p2 = xv0[2], p3 = xv0[3];
    const float4 q0 = xv1[0], q1 = xv1[1], q2 = xv1[2], q3 = xv1[3];

    float4 w[4][4];  // w[k][i] = W1[lane+32k][4i..4i+3]
#pragma unroll
    for (int k = 0; k < 4; k++) {
        const float4* w1 = reinterpret_cast<const float4*>(W1 + (lane + 32 * k) * D_DIM);
#pragma unroll
        for (int i = 0; i < 4; i++) w[k][i] = w1[i];
    }

    float w2v[4][O_DIM];  // W2[o][lane+32k]
#pragma unroll
    for (int k = 0; k < 4; k++)
#pragma unroll
        for (int o = 0; o < O_DIM; o++)
            w2v[k][o] = __ldg(W2 + o * H_DIM + lane + 32 * k);

    // ---------------- compute --------------------------------------------
    const float LOG2E_X2 = 2.8853900817779268f;  // 2*log2(e)
    float acc[16];  // [row*8 + o]
#pragma unroll
    for (int j = 0; j < 16; j++) acc[j] = 0.f;

#pragma unroll
    for (int k = 0; k < 4; k++) {
        const float4 wa = w[k][0], wb = w[k][1], wc = w[k][2], wd = w[k][3];

        // s = ||W1 row||^2 (shared by both batch rows)
        float s0 = wa.x * wa.x, s1 = wc.x * wc.x;
        s0 = fmaf(wa.y, wa.y, s0); s1 = fmaf(wc.y, wc.y, s1);
        s0 = fmaf(wa.z, wa.z, s0); s1 = fmaf(wc.z, wc.z, s1);
        s0 = fmaf(wa.w, wa.w, s0); s1 = fmaf(wc.w, wc.w, s1);
        s0 = fmaf(wb.x, wb.x, s0); s1 = fmaf(wd.x, wd.x, s1);
        s0 = fmaf(wb.y, wb.y, s0); s1 = fmaf(wd.y, wd.y, s1);
        s0 = fmaf(wb.z, wb.z, s0); s1 = fmaf(wd.z, wd.z, s1);
        s0 = fmaf(wb.w, wb.w, s0); s1 = fmaf(wd.w, wd.w, s1);
        const float s  = s0 + s1;
        const float s2 = s * s;

        // a for row 0 (two parallel chains) and row 1 (two parallel chains)
        float aA = wa.x * p0.x, aB = wc.x * p2.x;
        float cA = wa.x * q0.x, cB = wc.x * q2.x;
        aA = fmaf(wa.y, p0.y, aA); aB = fmaf(wc.y, p2.y, aB);
        cA = fmaf(wa.y, q0.y, cA); cB = fmaf(wc.y, q2.y, cB);
        aA = fmaf(wa.z, p0.z, aA); aB = fmaf(wc.z, p2.z, aB);
        cA = fmaf(wa.z, q0.z, cA); cB = fmaf(wc.z, q2.z, cB);
        aA = fmaf(wa.w, p0.w, aA); aB = fmaf(wc.w, p2.w, aB);
        cA = fmaf(wa.w, q0.w, cA); cB = fmaf(wc.w, q2.w, cB);
        aA = fmaf(wb.x, p1.x, aA); aB = fmaf(wd.x, p3.x, aB);
        cA = fmaf(wb.x, q1.x, cA); cB = fmaf(wd.x, q3.x, cB);
        aA = fmaf(wb.y, p1.y, aA); aB = fmaf(wd.y, p3.y, aB);
        cA = fmaf(wb.y, q1.y, cA); cB = fmaf(wd.y, q3.y, cB);
        aA = fmaf(wb.z, p1.z, aA); aB = fmaf(wd.z, p3.z, aB);
        cA = fmaf(wb.z, q1.z, cA); cB = fmaf(wd.z, q3.z, cB);
        aA = fmaf(wb.w, p1.w, aA); aB = fmaf(wd.w, p3.w, aB);
        cA = fmaf(wb.w, q1.w, cA); cB = fmaf(wd.w, q3.w, cB);
        const float a_r0 = aA + aB;
        const float a_r1 = cA + cB;

        // tanh'''' for both rows (independent MUFU chains)
        const float e0  = ex2_approx(a_r0 * LOG2E_X2);
        const float e1  = ex2_approx(a_r1 * LOG2E_X2);
        const float t0  = fmaf(-2.f, rcp_approx(e0 + 1.f), 1.f);
        const float t1  = fmaf(-2.f, rcp_approx(e1 + 1.f), 1.f);
        const float t0sq = t0 * t0, t1sq = t1 * t1;
        const float g0  = 8.f * t0 * (1.f - t0sq) * (2.f - 3.f * t0sq);
        const float g1  = 8.f * t1 * (1.f - t1sq) * (2.f - 3.f * t1sq);
        const float c0  = g0 * s2;
        const float c1  = g1 * s2;

#pragma unroll
        for (int o = 0; o < O_DIM; o++) {
            acc[o]     = fmaf(c0, w2v[k][o], acc[o]);
            acc[8 + o] = fmaf(c1, w2v[k][o], acc[8 + o]);
        }
    }

    // ---------------- folded reduction: 16 shuffles, depth 5 --------------
    // acc[j], j = row*8+o. Each fold step halves live values; after step m,
    // lane bit (5-m) encodes the top bit of the surviving index range.
    const unsigned FULL = 0xffffffffu;

    float r8[8];
#pragma unroll
    for (int i = 0; i < 8; i++) {           // off=16: 16 -> 8
        float send = (lane & 16) ? acc[i] : acc[i + 8];
        float keep = (lane & 16) ? acc[i + 8] : acc[i];
        r8[i] = keep + __shfl_xor_sync(FULL, send, 16);
    }
    float r4[4];
#pragma unroll
    for (int i = 0; i < 4; i++) {           // off=8: 8 -> 4
        float send = (lane & 8) ? r8[i] : r8[i + 4];
        float keep = (lane & 8) ? r8[i + 4] : r8[i];
        r4[i] = keep + __shfl_xor_sync(FULL, send, 8);
    }
    float r2[2];
#pragma unroll
    for (int i = 0; i < 2; i++) {           // off=4: 4 -> 2
        float send = (lane & 4) ? r4[i] : r4[i + 2];
        float keep = (lane & 4) ? r4[i + 2] : r4[i];
        r2[i] = keep + __shfl_xor_sync(FULL, send, 4);
    }
    {                                       // off=2: 2 -> 1
        float send = (lane & 2) ? r2[0] : r2[1];
        float keep = (lane & 2) ? r2[1] : r2[0];
        r2[0] = keep + __shfl_xor_sync(FULL, send, 2);
    }
    float r = r2[0] + __shfl_xor_sync(FULL, r2[0], 1);  // off=1: finish

    // lane pair (lane>>1) holds index j = bit4*8 + bit3*4 + bit2*2 + bit1
    if ((lane & 1) == 0) {
        const int j = ((lane >> 1) & 15);
        const int row = j >> 3;      // 0 or 1
        const int o   = j & 7;
        out[(b0 + row) * O_DIM + o] = r;
    }
}

extern "C" void kernel_launch(void* const* d_in, const int* in_sizes, int n_in,
                              void* d_out, int out_size) {
    const float* x  = (const float*)d_in[0];   // 256*16
    const float* W1 = (const float*)d_in[1];   // 128*16
    const float* W2 = (const float*)d_in[2];   // 8*128
    float* out = (float*)d_out;                // 256*8
    // 32 blocks x 128 threads = 128 warps x 2 rows = 256 batch rows.
    bilap_kernel<<<32, 128>>>(x, W1, W2, out);
}